// round 12
// baseline (speedup 1.0000x reference)
#include <cuda_runtime.h>
#include <cuda_fp16.h>
#include <mma.h>
#include <cstdint>
#include <math.h>

using namespace nvcuda;

#define Bb 32
#define Ll 1024
#define Dd 768
#define SHIFT 120.0f

// ---------------------------------------------------------------------------
// Scratch (device globals; no allocation allowed)
// ---------------------------------------------------------------------------
__device__ float g_eatt[(size_t)Bb * Ll * Ll];   // exp(att - SHIFT)  [i][j]

__device__ __half g_in1hi[(size_t)Bb * Ll * Dd];
__device__ __half g_in1lo[(size_t)Bb * Ll * Dd];
__device__ __half g_in2hi[(size_t)Bb * Ll * Dd];
__device__ __half g_in2lo[(size_t)Bb * Ll * Dd];

__device__ float g_rsum[Bb * Ll];   // per-row sums -> inverted in place
__device__ float g_csum[Bb * Ll];   // per-col sums -> inverted in place

struct alignas(8) HF4 { __half v[4]; };

__device__ __forceinline__ HF4 split4(const float* vv, HF4& lo) {
    HF4 hi;
#pragma unroll
    for (int k = 0; k < 4; ++k) {
        hi.v[k] = __float2half_rn(vv[k]);
        lo.v[k] = __float2half_rn(vv[k] - __half2float(hi.v[k]));
    }
    return hi;
}

__device__ __forceinline__ uint32_t smem_u32(const void* p) {
    uint32_t a;
    asm("{ .reg .u64 t; cvta.to.shared.u64 t, %1; cvt.u32.u64 %0, t; }"
        : "=r"(a) : "l"(p));
    return a;
}

__device__ __forceinline__ void cp16(uint32_t dst, const void* src) {
    asm volatile("cp.async.cg.shared.global [%0], [%1], 16;" :: "r"(dst), "l"(src));
}
#define CP_COMMIT() asm volatile("cp.async.commit_group;" ::: "memory")
#define CP_WAIT(n)  asm volatile("cp.async.wait_group %0;" :: "n"(n) : "memory")

__device__ __forceinline__ uint32_t pack2(float a, float b) {
    __half2 h = __floats2half2_rn(a, b);
    return *reinterpret_cast<uint32_t*>(&h);
}

// ---------------------------------------------------------------------------
// Elementwise split fp32 -> fp16 hi/lo for both inputs; zeroes rsum/csum.
// ---------------------------------------------------------------------------
__global__ __launch_bounds__(256)
void k_split2(const float* __restrict__ in1, const float* __restrict__ in2,
              __half* __restrict__ hi1, __half* __restrict__ lo1,
              __half* __restrict__ hi2, __half* __restrict__ lo2,
              float* __restrict__ rsum, float* __restrict__ csum) {
    if (blockIdx.y == 0 && blockIdx.x < 64) {
        int idx = blockIdx.x * 1024 + threadIdx.x * 4;
        float4 z = {0.f, 0.f, 0.f, 0.f};
        if (idx < Bb * Ll) *(float4*)&rsum[idx] = z;
        else               *(float4*)&csum[idx - Bb * Ll] = z;
    }
    const float* src = blockIdx.y ? in2 : in1;
    __half* hi = blockIdx.y ? hi2 : hi1;
    __half* lo = blockIdx.y ? lo2 : lo1;
    size_t base = ((size_t)blockIdx.x * 256 + threadIdx.x) * 4;
    float4 v = *(const float4*)&src[base];
    float vv[4] = {v.x, v.y, v.z, v.w};
    HF4 l4; HF4 h4 = split4(vv, l4);
    *(HF4*)&hi[base] = h4;
    *(HF4*)&lo[base] = l4;
}

// ---------------------------------------------------------------------------
// Scores GEMM: 3-product fp16 (hh+lh+hl), CTA 128x128, KC=32, 2-stage.
// Epilogue: e = exp(v-SHIFT), row/col sums via atomicAdd, writes e.
// ---------------------------------------------------------------------------
#define KC 32
#define AP 40            // [M,K]-tile pitch in halves (80B rows)
#define BP 136           // [K,N]-tile pitch in halves (272B rows)
#define TILE_MK (128 * AP * 2)   // 10240 bytes
#define S_STAGE (4 * TILE_MK)    // 40960 bytes (Ahi,Alo,Bhi,Blo)

__global__ __launch_bounds__(256, 2)
void k_scores(const __half* __restrict__ Ahi, const __half* __restrict__ Alo,
              const __half* __restrict__ Bhi, const __half* __restrict__ Blo,
              float* __restrict__ C,
              float* __restrict__ rsum, float* __restrict__ csum) {
    extern __shared__ char sm[];
    const uint32_t sbase = smem_u32(sm);

    int tid = threadIdx.x;
    int wid = tid >> 5;
    int wm  = wid & 3;
    int wn  = wid >> 2;
    int b   = blockIdx.z;
    int m0  = blockIdx.y * 128;
    int n0  = blockIdx.x * 128;

    const __half* Ah = Ahi + (size_t)b * Ll * Dd + (size_t)m0 * Dd;
    const __half* Al = Alo + (size_t)b * Ll * Dd + (size_t)m0 * Dd;
    const __half* Bh = Bhi + (size_t)b * Ll * Dd + (size_t)n0 * Dd;
    const __half* Bl = Blo + (size_t)b * Ll * Dd + (size_t)n0 * Dd;

    int arow = tid >> 2;            // 0..63 (x2 -> 128 rows)
    int ac16 = (tid & 3) * 8;       // covers KC=32 halves

    auto load_stage = [&](int st, int k0) {
        uint32_t s = sbase + st * S_STAGE;
#pragma unroll
        for (int h = 0; h < 2; ++h) {
            int r = arow + h * 64;
            uint32_t d = s + r * (AP * 2) + ac16 * 2;
            cp16(d,                Ah + (size_t)r * Dd + k0 + ac16);
            cp16(d + TILE_MK,      Al + (size_t)r * Dd + k0 + ac16);
            cp16(d + 2 * TILE_MK,  Bh + (size_t)r * Dd + k0 + ac16);
            cp16(d + 3 * TILE_MK,  Bl + (size_t)r * Dd + k0 + ac16);
        }
    };

    wmma::fragment<wmma::accumulator, 16, 16, 16, float> acc[2][4];
#pragma unroll
    for (int i = 0; i < 2; ++i)
#pragma unroll
        for (int j = 0; j < 4; ++j)
            wmma::fill_fragment(acc[i][j], 0.0f);

    const int NK = Dd / KC;
    load_stage(0, 0);
    CP_COMMIT();

    for (int it = 0; it < NK; ++it) {
        if (it + 1 < NK) {
            load_stage((it + 1) & 1, (it + 1) * KC);
            CP_COMMIT();
            CP_WAIT(1);
        } else {
            CP_WAIT(0);
        }
        __syncthreads();

        const __half* sA0 = (const __half*)(sm + (it & 1) * S_STAGE);
        const __half* sAl = sA0 + TILE_MK / 2;
        const __half* sB0 = sA0 + TILE_MK;
        const __half* sBl = sA0 + 3 * TILE_MK / 2;

#pragma unroll
        for (int ks = 0; ks < KC / 16; ++ks) {
            wmma::fragment<wmma::matrix_a, 16, 16, 16, __half, wmma::row_major> ah[2], al[2];
#pragma unroll
            for (int fi = 0; fi < 2; ++fi) {
                int ro = (wm * 32 + fi * 16) * AP + ks * 16;
                wmma::load_matrix_sync(ah[fi], &sA0[ro], AP);
                wmma::load_matrix_sync(al[fi], &sAl[ro], AP);
            }
#pragma unroll
            for (int fj = 0; fj < 4; ++fj) {
                wmma::fragment<wmma::matrix_b, 16, 16, 16, __half, wmma::col_major> bh, bl;
                int ro = (wn * 64 + fj * 16) * AP + ks * 16;
                wmma::load_matrix_sync(bh, &sB0[ro], AP);
                wmma::load_matrix_sync(bl, &sBl[ro], AP);
#pragma unroll
                for (int fi = 0; fi < 2; ++fi) {
                    wmma::mma_sync(acc[fi][fj], ah[fi], bh, acc[fi][fj]);
                    wmma::mma_sync(acc[fi][fj], al[fi], bh, acc[fi][fj]);
                    wmma::mma_sync(acc[fi][fj], ah[fi], bl, acc[fi][fj]);
                }
            }
        }
        __syncthreads();
    }

    // --- Epilogue: exp + row/col sums + e write ---
    float* Cb = C + (size_t)b * Ll * Ll;
    float* Sf = (float*)sm;   // 128 x 132 fp32 = 67584 B
#pragma unroll
    for (int fi = 0; fi < 2; ++fi)
#pragma unroll
        for (int fj = 0; fj < 4; ++fj) {
            int lr = wm * 32 + fi * 16;
            int lc = wn * 64 + fj * 16;
            wmma::store_matrix_sync(&Sf[lr * 132 + lc], acc[fi][fj], 132,
                                    wmma::mem_row_major);
        }
    __syncthreads();

    {   // row pass: exp in place + row sums
        int r = tid >> 1, half = tid & 1;
        float* row = Sf + r * 132 + half * 64;
        float s = 0.f;
#pragma unroll 8
        for (int c = 0; c < 64; ++c) {
            float e = __expf(row[c] - SHIFT);
            row[c] = e;
            s += e;
        }
        s += __shfl_xor_sync(0xffffffffu, s, 1);
        if (!half) atomicAdd(&rsum[(size_t)b * Ll + m0 + r], s);
    }
    __syncthreads();

    {   // col pass
        int c = tid >> 1, half = tid & 1;
        float s = 0.f;
#pragma unroll 8
        for (int r = 0; r < 64; ++r)
            s += Sf[(half * 64 + r) * 132 + c];
        s += __shfl_xor_sync(0xffffffffu, s, 1);
        if (!half) atomicAdd(&csum[(size_t)b * Ll + n0 + c], s);
    }
    __syncthreads();

#pragma unroll 4
    for (int it2 = 0; it2 < 16; ++it2) {
        int q  = tid + it2 * 256;
        int ii = q >> 5;
        int c4 = (q & 31) * 4;
        float4 v = *(float4*)&Sf[ii * 132 + c4];
        *(float4*)&Cb[(size_t)(m0 + ii) * Ll + n0 + c4] = v;
    }
}

// ---------------------------------------------------------------------------
// Invert sums in place
// ---------------------------------------------------------------------------
__global__ __launch_bounds__(256)
void k_invert(float* __restrict__ rsum, float* __restrict__ csum) {
    int i = blockIdx.x * 256 + threadIdx.x;
    float* p = (i < Bb * Ll) ? (rsum + i) : (csum + i - Bb * Ll);
    *p = 1.0f / *p;
}

// ---------------------------------------------------------------------------
// Merged output GEMMs, normalization fused into the A-loader.
// KC2=32, A: e (fp32) LDG -> scale -> fp16 smem; B: in-hi fp16 cp.async.
//   A_COL=true  (outA): out[j,d] = sum_i (e[i,j]*csinv[j]) * in1[i,d]
//                       A-tile [K=32 i-rows x 128 j-cols], col_major frags
//   A_COL=false (outB): out[i,d] = sum_j (e[i,j]*rsinv[i]) * in2[j,d]
//                       A-tile [128 i-rows x K=32 j-cols], row_major frags
// ---------------------------------------------------------------------------
#define KC2 32
#define A16_COL (KC2 * BP * 2)    // 8704  bytes: 32 x 128 halves (pitch 136)
#define A16_ROW (128 * AP * 2)    // 10240 bytes: 128 x 32 halves (pitch 40)
#define B16T    (KC2 * BP * 2)    // 8704  bytes: 32 x 128 halves

template <bool A_COL>
__device__ __forceinline__
void out_body(const float* __restrict__ E, const __half* __restrict__ IN,
              const float* __restrict__ inv, float* __restrict__ out,
              int b, char* sm) {
    const uint32_t sbase = smem_u32(sm);
    constexpr int ATILE = A_COL ? A16_COL : A16_ROW;

    int tid = threadIdx.x;
    int wid = tid >> 5;
    int wm  = wid & 3;
    int wn  = wid >> 2;
    int m0  = blockIdx.y * 128;
    int n0  = blockIdx.x * 128;

    const float*  Eb  = E  + (size_t)b * Ll * Ll;
    const __half* INb = IN + (size_t)b * Ll * Dd + n0;

    // --- prologue: loop-invariant scale values ---
    float4 csv;            // outA: per-thread 4 column scales
    float  rsv[4];         // outB: per-thread 4 row scales
    if (A_COL) {
        csv = *(const float4*)&inv[(size_t)b * Ll + m0 + (tid & 31) * 4];
    } else {
#pragma unroll
        for (int l = 0; l < 4; ++l)
            rsv[l] = inv[(size_t)b * Ll + m0 + l * 32 + (tid >> 3)];
    }

    // B cp.async map
    int brow = tid >> 4;            // 0..15 (x2 -> 32 rows)
    int bc16 = (tid & 15) * 8;      // covers 128 cols

    auto cp_B = [&](int st, int k0) {
        uint32_t s = sbase + 2 * ATILE + st * B16T;
#pragma unroll
        for (int h = 0; h < 2; ++h) {
            int r = brow + h * 16;
            cp16(s + r * (BP * 2) + bc16 * 2, INb + (size_t)(k0 + r) * Dd + bc16);
        }
    };

    // A LDG: 4 x float4 per thread per stage (fully coalesced rows)
    auto ldg_A = [&](int k0, float4 (&r)[4]) {
#pragma unroll
        for (int l = 0; l < 4; ++l) {
            if (A_COL) {
                int row = l * 8 + (tid >> 5);           // i
                int c   = (tid & 31) * 4;               // j
                r[l] = *(const float4*)&Eb[(size_t)(k0 + row) * Ll + m0 + c];
            } else {
                int row = l * 32 + (tid >> 3);          // i
                int c   = (tid & 7) * 4;                // j
                r[l] = *(const float4*)&Eb[(size_t)(m0 + row) * Ll + k0 + c];
            }
        }
    };

    // scale + convert + STS into fp16 A-tile
    auto cvt_A = [&](int st, float4 (&r)[4]) {
        __half* A16 = (__half*)(sm + st * ATILE);
#pragma unroll
        for (int l = 0; l < 4; ++l) {
            uint2 h;
            if (A_COL) {
                int row = l * 8 + (tid >> 5);
                int c   = (tid & 31) * 4;
                h.x = pack2(r[l].x * csv.x, r[l].y * csv.y);
                h.y = pack2(r[l].z * csv.z, r[l].w * csv.w);
                *(uint2*)&A16[row * BP + c] = h;
            } else {
                int row = l * 32 + (tid >> 3);
                int c   = (tid & 7) * 4;
                float s = rsv[l];
                h.x = pack2(r[l].x * s, r[l].y * s);
                h.y = pack2(r[l].z * s, r[l].w * s);
                *(uint2*)&A16[row * AP + c] = h;
            }
        }
    };

    wmma::fragment<wmma::accumulator, 16, 16, 16, float> acc[2][4];
#pragma unroll
    for (int i = 0; i < 2; ++i)
#pragma unroll
        for (int j = 0; j < 4; ++j)
            wmma::fill_fragment(acc[i][j], 0.0f);

    const int NK = Ll / KC2;   // 32
    float4 r[4];

    // prologue: stage 0 A (convert immediately), B(0); prefetch A(1)
    cp_B(0, 0);
    CP_COMMIT();
    ldg_A(0, r);
    cvt_A(0, r);
    ldg_A(KC2, r);

    for (int it = 0; it < NK; ++it) {
        if (it + 1 < NK) {
            cp_B((it + 1) & 1, (it + 1) * KC2);
            CP_COMMIT();
            CP_WAIT(1);
        } else {
            CP_WAIT(0);
        }
        __syncthreads();

        // compute(it)
        {
            const __half* sA0 = (const __half*)(sm + (it & 1) * ATILE);
            const __half* sB0 = (const __half*)(sm + 2 * ATILE + (it & 1) * B16T);
#pragma unroll
            for (int ks = 0; ks < KC2 / 16; ++ks) {
                if constexpr (A_COL) {
                    wmma::fragment<wmma::matrix_a, 16, 16, 16, __half, wmma::col_major> ah[2];
#pragma unroll
                    for (int fi = 0; fi < 2; ++fi) {
                        int ro = (ks * 16) * BP + wm * 32 + fi * 16;
                        wmma::load_matrix_sync(ah[fi], &sA0[ro], BP);
                    }
#pragma unroll
                    for (int fj = 0; fj < 4; ++fj) {
                        wmma::fragment<wmma::matrix_b, 16, 16, 16, __half, wmma::row_major> bh;
                        int ro = (ks * 16) * BP + wn * 64 + fj * 16;
                        wmma::load_matrix_sync(bh, &sB0[ro], BP);
#pragma unroll
                        for (int fi = 0; fi < 2; ++fi)
                            wmma::mma_sync(acc[fi][fj], ah[fi], bh, acc[fi][fj]);
                    }
                } else {
                    wmma::fragment<wmma::matrix_a, 16, 16, 16, __half, wmma::row_major> ah[2];
#pragma unroll
                    for (int fi = 0; fi < 2; ++fi) {
                        int ro = (wm * 32 + fi * 16) * AP + ks * 16;
                        wmma::load_matrix_sync(ah[fi], &sA0[ro], AP);
                    }
#pragma unroll
                    for (int fj = 0; fj < 4; ++fj) {
                        wmma::fragment<wmma::matrix_b, 16, 16, 16, __half, wmma::row_major> bh;
                        int ro = (ks * 16) * BP + wn * 64 + fj * 16;
                        wmma::load_matrix_sync(bh, &sB0[ro], BP);
#pragma unroll
                        for (int fi = 0; fi < 2; ++fi)
                            wmma::mma_sync(acc[fi][fj], ah[fi], bh, acc[fi][fj]);
                    }
                }
            }
        }

        // stage it+1: convert held regs; prefetch it+2
        if (it + 1 < NK) {
            cvt_A((it + 1) & 1, r);
            if (it + 2 < NK) ldg_A((it + 2) * KC2, r);
        }
        __syncthreads();
    }

    float* Cb = out + (size_t)b * Ll * Dd;
#pragma unroll
    for (int fi = 0; fi < 2; ++fi)
#pragma unroll
        for (int fj = 0; fj < 4; ++fj) {
            int gr = m0 + wm * 32 + fi * 16;
            int gc = n0 + wn * 64 + fj * 16;
            wmma::store_matrix_sync(&Cb[(size_t)gr * Dd + gc], acc[fi][fj], Dd,
                                    wmma::mem_row_major);
        }
}

__global__ __launch_bounds__(256, 2)
void k_out(const float* __restrict__ eatt,
           const float* __restrict__ rsinv, const float* __restrict__ csinv,
           const __half* __restrict__ i1h, const __half* __restrict__ i2h,
           float* __restrict__ out) {
    extern __shared__ char sm[];
    int z = blockIdx.z;
    if (z < Bb) out_body<true >(eatt, i1h, csinv, out, z, sm);
    else        out_body<false>(eatt, i2h, rsinv, out + (size_t)Bb * Ll * Dd, z - Bb, sm);
}

// ---------------------------------------------------------------------------
extern "C" void kernel_launch(void* const* d_in, const int* in_sizes, int n_in,
                              void* d_out, int out_size) {
    const float* in1 = (const float*)d_in[0];
    const float* in2 = (const float*)d_in[1];
    float* out = (float*)d_out;

    const int SMEM_SCORES = 2 * S_STAGE;                 // 81920
    const int SMEM_OUT    = 2 * A16_ROW + 2 * B16T;      // 37888 (row variant max)
    cudaFuncSetAttribute(k_scores, cudaFuncAttributeMaxDynamicSharedMemorySize, SMEM_SCORES);
    cudaFuncSetAttribute(k_out,    cudaFuncAttributeMaxDynamicSharedMemorySize, SMEM_OUT);

    float *eatt, *rsum, *csum;
    __half *i1h, *i1l, *i2h, *i2l;
    cudaGetSymbolAddress((void**)&eatt, g_eatt);
    cudaGetSymbolAddress((void**)&rsum, g_rsum);
    cudaGetSymbolAddress((void**)&csum, g_csum);
    cudaGetSymbolAddress((void**)&i1h,  g_in1hi);
    cudaGetSymbolAddress((void**)&i1l,  g_in1lo);
    cudaGetSymbolAddress((void**)&i2h,  g_in2hi);
    cudaGetSymbolAddress((void**)&i2l,  g_in2lo);

    // 1) split inputs to fp16 hi/lo (+ zero rsum/csum)
    int sblk = (int)(((size_t)Bb * Ll * Dd) / (256 * 4));
    k_split2<<<dim3(sblk, 2), 256>>>(in1, in2, i1h, i1l, i2h, i2l, rsum, csum);

    // 2) scores GEMM (3 products) + fused exp/row-sum/col-sum epilogue -> eatt
    k_scores<<<dim3(Ll / 128, Ll / 128, Bb), 256, SMEM_SCORES>>>(
        i1h, i1l, i2h, i2l, eatt, rsum, csum);

    // 3) invert sums
    k_invert<<<(2 * Bb * Ll) / 256, 256>>>(rsum, csum);

    // 4) merged output GEMMs with fused normalization (reads eatt directly)
    k_out<<<dim3(Dd / 128, Ll / 128, 2 * Bb), 256, SMEM_OUT>>>(
        eatt, rsum, csum, i1h, i2h, out);
}

// round 13
// speedup vs baseline: 1.0106x; 1.0106x over previous
#include <cuda_runtime.h>
#include <cuda_fp16.h>
#include <mma.h>
#include <cstdint>
#include <math.h>

using namespace nvcuda;

#define Bb 32
#define Ll 1024
#define Dd 768
#define SHIFT 120.0f

// ---------------------------------------------------------------------------
// Scratch (device globals; no allocation allowed)
// ---------------------------------------------------------------------------
__device__ float g_eatt[(size_t)Bb * Ll * Ll];   // exp(att - SHIFT)  [i][j]

__device__ __half g_in1hi[(size_t)Bb * Ll * Dd];
__device__ __half g_in1lo[(size_t)Bb * Ll * Dd];
__device__ __half g_in2hi[(size_t)Bb * Ll * Dd];
__device__ __half g_in2lo[(size_t)Bb * Ll * Dd];

__device__ float g_rsum[Bb * Ll];   // per-row exp sums (raw)
__device__ float g_csum[Bb * Ll];   // per-col exp sums (raw)

struct alignas(8) HF4 { __half v[4]; };

__device__ __forceinline__ HF4 split4(const float* vv, HF4& lo) {
    HF4 hi;
#pragma unroll
    for (int k = 0; k < 4; ++k) {
        hi.v[k] = __float2half_rn(vv[k]);
        lo.v[k] = __float2half_rn(vv[k] - __half2float(hi.v[k]));
    }
    return hi;
}

__device__ __forceinline__ uint32_t smem_u32(const void* p) {
    uint32_t a;
    asm("{ .reg .u64 t; cvta.to.shared.u64 t, %1; cvt.u32.u64 %0, t; }"
        : "=r"(a) : "l"(p));
    return a;
}

__device__ __forceinline__ void cp16(uint32_t dst, const void* src) {
    asm volatile("cp.async.cg.shared.global [%0], [%1], 16;" :: "r"(dst), "l"(src));
}
#define CP_COMMIT() asm volatile("cp.async.commit_group;" ::: "memory")
#define CP_WAIT(n)  asm volatile("cp.async.wait_group %0;" :: "n"(n) : "memory")

__device__ __forceinline__ uint32_t pack2(float a, float b) {
    __half2 h = __floats2half2_rn(a, b);
    return *reinterpret_cast<uint32_t*>(&h);
}

// ---------------------------------------------------------------------------
// Elementwise split fp32 -> fp16 hi/lo for both inputs; zeroes rsum/csum.
// ---------------------------------------------------------------------------
__global__ __launch_bounds__(256)
void k_split2(const float* __restrict__ in1, const float* __restrict__ in2,
              __half* __restrict__ hi1, __half* __restrict__ lo1,
              __half* __restrict__ hi2, __half* __restrict__ lo2,
              float* __restrict__ rsum, float* __restrict__ csum) {
    if (blockIdx.y == 0 && blockIdx.x < 64) {
        int idx = blockIdx.x * 1024 + threadIdx.x * 4;
        float4 z = {0.f, 0.f, 0.f, 0.f};
        if (idx < Bb * Ll) *(float4*)&rsum[idx] = z;
        else               *(float4*)&csum[idx - Bb * Ll] = z;
    }
    const float* src = blockIdx.y ? in2 : in1;
    __half* hi = blockIdx.y ? hi2 : hi1;
    __half* lo = blockIdx.y ? lo2 : lo1;
    size_t base = ((size_t)blockIdx.x * 256 + threadIdx.x) * 4;
    float4 v = *(const float4*)&src[base];
    float vv[4] = {v.x, v.y, v.z, v.w};
    HF4 l4; HF4 h4 = split4(vv, l4);
    *(HF4*)&hi[base] = h4;
    *(HF4*)&lo[base] = l4;
}

// ---------------------------------------------------------------------------
// Scores GEMM: 3-product fp16 (hh+lh+hl), CTA 128x128, KC=32, 2-stage.
// Epilogue: e = exp(v-SHIFT), row/col sums via atomicAdd, writes e.
// ---------------------------------------------------------------------------
#define KC 32
#define AP 40            // [M,K]-tile pitch in halves (80B rows)
#define BP 136           // [K,N]-tile pitch in halves (272B rows)
#define TILE_MK (128 * AP * 2)   // 10240 bytes
#define S_STAGE (4 * TILE_MK)    // 40960 bytes (Ahi,Alo,Bhi,Blo)

__global__ __launch_bounds__(256, 2)
void k_scores(const __half* __restrict__ Ahi, const __half* __restrict__ Alo,
              const __half* __restrict__ Bhi, const __half* __restrict__ Blo,
              float* __restrict__ C,
              float* __restrict__ rsum, float* __restrict__ csum) {
    extern __shared__ char sm[];
    const uint32_t sbase = smem_u32(sm);

    int tid = threadIdx.x;
    int wid = tid >> 5;
    int wm  = wid & 3;
    int wn  = wid >> 2;
    int b   = blockIdx.z;
    int m0  = blockIdx.y * 128;
    int n0  = blockIdx.x * 128;

    const __half* Ah = Ahi + (size_t)b * Ll * Dd + (size_t)m0 * Dd;
    const __half* Al = Alo + (size_t)b * Ll * Dd + (size_t)m0 * Dd;
    const __half* Bh = Bhi + (size_t)b * Ll * Dd + (size_t)n0 * Dd;
    const __half* Bl = Blo + (size_t)b * Ll * Dd + (size_t)n0 * Dd;

    int arow = tid >> 2;            // 0..63 (x2 -> 128 rows)
    int ac16 = (tid & 3) * 8;       // covers KC=32 halves

    auto load_stage = [&](int st, int k0) {
        uint32_t s = sbase + st * S_STAGE;
#pragma unroll
        for (int h = 0; h < 2; ++h) {
            int r = arow + h * 64;
            uint32_t d = s + r * (AP * 2) + ac16 * 2;
            cp16(d,                Ah + (size_t)r * Dd + k0 + ac16);
            cp16(d + TILE_MK,      Al + (size_t)r * Dd + k0 + ac16);
            cp16(d + 2 * TILE_MK,  Bh + (size_t)r * Dd + k0 + ac16);
            cp16(d + 3 * TILE_MK,  Bl + (size_t)r * Dd + k0 + ac16);
        }
    };

    wmma::fragment<wmma::accumulator, 16, 16, 16, float> acc[2][4];
#pragma unroll
    for (int i = 0; i < 2; ++i)
#pragma unroll
        for (int j = 0; j < 4; ++j)
            wmma::fill_fragment(acc[i][j], 0.0f);

    const int NK = Dd / KC;
    load_stage(0, 0);
    CP_COMMIT();

    for (int it = 0; it < NK; ++it) {
        if (it + 1 < NK) {
            load_stage((it + 1) & 1, (it + 1) * KC);
            CP_COMMIT();
            CP_WAIT(1);
        } else {
            CP_WAIT(0);
        }
        __syncthreads();

        const __half* sA0 = (const __half*)(sm + (it & 1) * S_STAGE);
        const __half* sAl = sA0 + TILE_MK / 2;
        const __half* sB0 = sA0 + TILE_MK;
        const __half* sBl = sA0 + 3 * TILE_MK / 2;

#pragma unroll
        for (int ks = 0; ks < KC / 16; ++ks) {
            wmma::fragment<wmma::matrix_a, 16, 16, 16, __half, wmma::row_major> ah[2], al[2];
#pragma unroll
            for (int fi = 0; fi < 2; ++fi) {
                int ro = (wm * 32 + fi * 16) * AP + ks * 16;
                wmma::load_matrix_sync(ah[fi], &sA0[ro], AP);
                wmma::load_matrix_sync(al[fi], &sAl[ro], AP);
            }
#pragma unroll
            for (int fj = 0; fj < 4; ++fj) {
                wmma::fragment<wmma::matrix_b, 16, 16, 16, __half, wmma::col_major> bh, bl;
                int ro = (wn * 64 + fj * 16) * AP + ks * 16;
                wmma::load_matrix_sync(bh, &sB0[ro], AP);
                wmma::load_matrix_sync(bl, &sBl[ro], AP);
#pragma unroll
                for (int fi = 0; fi < 2; ++fi) {
                    wmma::mma_sync(acc[fi][fj], ah[fi], bh, acc[fi][fj]);
                    wmma::mma_sync(acc[fi][fj], al[fi], bh, acc[fi][fj]);
                    wmma::mma_sync(acc[fi][fj], ah[fi], bl, acc[fi][fj]);
                }
            }
        }
        __syncthreads();
    }

    // --- Epilogue: exp + row/col sums + e write ---
    float* Cb = C + (size_t)b * Ll * Ll;
    float* Sf = (float*)sm;   // 128 x 132 fp32 = 67584 B
#pragma unroll
    for (int fi = 0; fi < 2; ++fi)
#pragma unroll
        for (int fj = 0; fj < 4; ++fj) {
            int lr = wm * 32 + fi * 16;
            int lc = wn * 64 + fj * 16;
            wmma::store_matrix_sync(&Sf[lr * 132 + lc], acc[fi][fj], 132,
                                    wmma::mem_row_major);
        }
    __syncthreads();

    {   // row pass: exp in place + row sums
        int r = tid >> 1, half = tid & 1;
        float* row = Sf + r * 132 + half * 64;
        float s = 0.f;
#pragma unroll 8
        for (int c = 0; c < 64; ++c) {
            float e = __expf(row[c] - SHIFT);
            row[c] = e;
            s += e;
        }
        s += __shfl_xor_sync(0xffffffffu, s, 1);
        if (!half) atomicAdd(&rsum[(size_t)b * Ll + m0 + r], s);
    }
    __syncthreads();

    {   // col pass
        int c = tid >> 1, half = tid & 1;
        float s = 0.f;
#pragma unroll 8
        for (int r = 0; r < 64; ++r)
            s += Sf[(half * 64 + r) * 132 + c];
        s += __shfl_xor_sync(0xffffffffu, s, 1);
        if (!half) atomicAdd(&csum[(size_t)b * Ll + n0 + c], s);
    }
    __syncthreads();

#pragma unroll 4
    for (int it2 = 0; it2 < 16; ++it2) {
        int q  = tid + it2 * 256;
        int ii = q >> 5;
        int c4 = (q & 31) * 4;
        float4 v = *(float4*)&Sf[ii * 132 + c4];
        *(float4*)&Cb[(size_t)(m0 + ii) * Ll + n0 + c4] = v;
    }
}

// ---------------------------------------------------------------------------
// Merged output GEMMs, normalization fused, 3-buffer ring, ONE barrier/iter.
// Local reciprocal of raw sums in prologue (k_invert eliminated).
//   A_COL=true  (outA): out[j,d] = sum_i (e[i,j]/csum[j]) * in1[i,d]
//   A_COL=false (outB): out[i,d] = sum_j (e[i,j]/rsum[i]) * in2[j,d]
// ---------------------------------------------------------------------------
#define KC2 32
#define A16_ROW (128 * AP * 2)    // 10240 bytes: 128 x 32 halves (pitch 40)
#define B16T    (KC2 * BP * 2)    // 8704  bytes: 32 x 128 halves (pitch 136)
#define O3_STAGE (A16_ROW + B16T) // 18944 bytes per ring stage (uniform)

template <bool A_COL>
__device__ __forceinline__
void out_body(const float* __restrict__ E, const __half* __restrict__ IN,
              const float* __restrict__ sums, float* __restrict__ out,
              int b, char* sm) {
    const uint32_t sbase = smem_u32(sm);

    int tid = threadIdx.x;
    int wid = tid >> 5;
    int wm  = wid & 3;
    int wn  = wid >> 2;
    int m0  = blockIdx.y * 128;
    int n0  = blockIdx.x * 128;

    const float*  Eb  = E  + (size_t)b * Ll * Ll;
    const __half* INb = IN + (size_t)b * Ll * Dd + n0;

    // --- prologue: loop-invariant reciprocal scales ---
    float4 csv;            // outA: per-thread 4 column scales
    float  rsv[4];         // outB: per-thread 4 row scales
    if (A_COL) {
        float4 s4 = *(const float4*)&sums[(size_t)b * Ll + m0 + (tid & 31) * 4];
        csv.x = 1.0f / s4.x;  csv.y = 1.0f / s4.y;
        csv.z = 1.0f / s4.z;  csv.w = 1.0f / s4.w;
    } else {
#pragma unroll
        for (int l = 0; l < 4; ++l)
            rsv[l] = 1.0f / sums[(size_t)b * Ll + m0 + l * 32 + (tid >> 3)];
    }

    // B cp.async map
    int brow = tid >> 4;            // 0..15 (x2 -> 32 rows)
    int bc16 = (tid & 15) * 8;      // covers 128 cols

    auto cp_B = [&](int st, int k0) {
        uint32_t s = sbase + st * O3_STAGE + A16_ROW;
#pragma unroll
        for (int h = 0; h < 2; ++h) {
            int r = brow + h * 16;
            cp16(s + r * (BP * 2) + bc16 * 2, INb + (size_t)(k0 + r) * Dd + bc16);
        }
    };

    // A LDG: 4 x float4 per thread per stage
    auto ldg_A = [&](int k0, float4 (&r)[4]) {
#pragma unroll
        for (int l = 0; l < 4; ++l) {
            if (A_COL) {
                int row = l * 8 + (tid >> 5);           // i
                int c   = (tid & 31) * 4;               // j
                r[l] = *(const float4*)&Eb[(size_t)(k0 + row) * Ll + m0 + c];
            } else {
                int row = l * 32 + (tid >> 3);          // i
                int c   = (tid & 7) * 4;                // j
                r[l] = *(const float4*)&Eb[(size_t)(m0 + row) * Ll + k0 + c];
            }
        }
    };

    // scale + convert + STS into fp16 A-tile
    auto cvt_A = [&](int st, float4 (&r)[4]) {
        __half* A16 = (__half*)(sm + st * O3_STAGE);
#pragma unroll
        for (int l = 0; l < 4; ++l) {
            uint2 h;
            if (A_COL) {
                int row = l * 8 + (tid >> 5);
                int c   = (tid & 31) * 4;
                h.x = pack2(r[l].x * csv.x, r[l].y * csv.y);
                h.y = pack2(r[l].z * csv.z, r[l].w * csv.w);
                *(uint2*)&A16[row * BP + c] = h;
            } else {
                int row = l * 32 + (tid >> 3);
                int c   = (tid & 7) * 4;
                float s = rsv[l];
                h.x = pack2(r[l].x * s, r[l].y * s);
                h.y = pack2(r[l].z * s, r[l].w * s);
                *(uint2*)&A16[row * AP + c] = h;
            }
        }
    };

    wmma::fragment<wmma::accumulator, 16, 16, 16, float> acc[2][4];
#pragma unroll
    for (int i = 0; i < 2; ++i)
#pragma unroll
        for (int j = 0; j < 4; ++j)
            wmma::fill_fragment(acc[i][j], 0.0f);

    const int NK = Ll / KC2;   // 32
    float4 r[4];

    // prologue: B(0), B(1) in flight; A(0) converted; A(1) held in regs
    cp_B(0, 0);
    CP_COMMIT();
    cp_B(1, KC2);
    CP_COMMIT();
    ldg_A(0, r);
    cvt_A(0, r);
    ldg_A(KC2, r);

    for (int it = 0; it < NK; ++it) {
        // guarantee B(it) landed
        if (it + 1 < NK) CP_WAIT(1);
        else             CP_WAIT(0);

        // stage A(it+1): convert held regs (writes buf (it+1)%3 — disjoint from
        // any laggard compute(it-1) reading (it+2)%3); prefetch A(it+2)
        if (it + 1 < NK) {
            cvt_A((it + 1) % 3, r);
            if (it + 2 < NK) ldg_A((it + 2) * KC2, r);
        }

        __syncthreads();   // ONE barrier per iteration

        // B(it+2) into buf (it+2)%3 (safe only after barrier: laggards in
        // compute(it-1) read that same buffer)
        if (it + 2 < NK) {
            cp_B((it + 2) % 3, (it + 2) * KC2);
            CP_COMMIT();
        }

        // compute(it) on buf it%3
        {
            const __half* sA0 = (const __half*)(sm + (it % 3) * O3_STAGE);
            const __half* sB0 = (const __half*)(sm + (it % 3) * O3_STAGE + A16_ROW);
#pragma unroll
            for (int ks = 0; ks < KC2 / 16; ++ks) {
                if constexpr (A_COL) {
                    wmma::fragment<wmma::matrix_a, 16, 16, 16, __half, wmma::col_major> ah[2];
#pragma unroll
                    for (int fi = 0; fi < 2; ++fi) {
                        int ro = (ks * 16) * BP + wm * 32 + fi * 16;
                        wmma::load_matrix_sync(ah[fi], &sA0[ro], BP);
                    }
#pragma unroll
                    for (int fj = 0; fj < 4; ++fj) {
                        wmma::fragment<wmma::matrix_b, 16, 16, 16, __half, wmma::row_major> bh;
                        int ro = (ks * 16) * BP + wn * 64 + fj * 16;
                        wmma::load_matrix_sync(bh, &sB0[ro], BP);
#pragma unroll
                        for (int fi = 0; fi < 2; ++fi)
                            wmma::mma_sync(acc[fi][fj], ah[fi], bh, acc[fi][fj]);
                    }
                } else {
                    wmma::fragment<wmma::matrix_a, 16, 16, 16, __half, wmma::row_major> ah[2];
#pragma unroll
                    for (int fi = 0; fi < 2; ++fi) {
                        int ro = (wm * 32 + fi * 16) * AP + ks * 16;
                        wmma::load_matrix_sync(ah[fi], &sA0[ro], AP);
                    }
#pragma unroll
                    for (int fj = 0; fj < 4; ++fj) {
                        wmma::fragment<wmma::matrix_b, 16, 16, 16, __half, wmma::row_major> bh;
                        int ro = (ks * 16) * BP + wn * 64 + fj * 16;
                        wmma::load_matrix_sync(bh, &sB0[ro], BP);
#pragma unroll
                        for (int fi = 0; fi < 2; ++fi)
                            wmma::mma_sync(acc[fi][fj], ah[fi], bh, acc[fi][fj]);
                    }
                }
            }
        }
    }

    float* Cb = out + (size_t)b * Ll * Dd;
#pragma unroll
    for (int fi = 0; fi < 2; ++fi)
#pragma unroll
        for (int fj = 0; fj < 4; ++fj) {
            int gr = m0 + wm * 32 + fi * 16;
            int gc = n0 + wn * 64 + fj * 16;
            wmma::store_matrix_sync(&Cb[(size_t)gr * Dd + gc], acc[fi][fj], Dd,
                                    wmma::mem_row_major);
        }
}

__global__ __launch_bounds__(256, 2)
void k_out(const float* __restrict__ eatt,
           const float* __restrict__ rsum, const float* __restrict__ csum,
           const __half* __restrict__ i1h, const __half* __restrict__ i2h,
           float* __restrict__ out) {
    extern __shared__ char sm[];
    int z = blockIdx.z;
    if (z < Bb) out_body<true >(eatt, i1h, csum, out, z, sm);
    else        out_body<false>(eatt, i2h, rsum, out + (size_t)Bb * Ll * Dd, z - Bb, sm);
}

// ---------------------------------------------------------------------------
extern "C" void kernel_launch(void* const* d_in, const int* in_sizes, int n_in,
                              void* d_out, int out_size) {
    const float* in1 = (const float*)d_in[0];
    const float* in2 = (const float*)d_in[1];
    float* out = (float*)d_out;

    const int SMEM_SCORES = 2 * S_STAGE;   // 81920 (epilogue 67584 fits)
    const int SMEM_OUT    = 3 * O3_STAGE;  // 56832
    cudaFuncSetAttribute(k_scores, cudaFuncAttributeMaxDynamicSharedMemorySize, SMEM_SCORES);
    cudaFuncSetAttribute(k_out,    cudaFuncAttributeMaxDynamicSharedMemorySize, SMEM_OUT);

    float *eatt, *rsum, *csum;
    __half *i1h, *i1l, *i2h, *i2l;
    cudaGetSymbolAddress((void**)&eatt, g_eatt);
    cudaGetSymbolAddress((void**)&rsum, g_rsum);
    cudaGetSymbolAddress((void**)&csum, g_csum);
    cudaGetSymbolAddress((void**)&i1h,  g_in1hi);
    cudaGetSymbolAddress((void**)&i1l,  g_in1lo);
    cudaGetSymbolAddress((void**)&i2h,  g_in2hi);
    cudaGetSymbolAddress((void**)&i2l,  g_in2lo);

    // 1) split inputs to fp16 hi/lo (+ zero rsum/csum)
    int sblk = (int)(((size_t)Bb * Ll * Dd) / (256 * 4));
    k_split2<<<dim3(sblk, 2), 256>>>(in1, in2, i1h, i1l, i2h, i2l, rsum, csum);

    // 2) scores GEMM (3 products) + fused exp/row-sum/col-sum epilogue -> eatt
    k_scores<<<dim3(Ll / 128, Ll / 128, Bb), 256, SMEM_SCORES>>>(
        i1h, i1l, i2h, i2l, eatt, rsum, csum);

    // 3) merged output GEMMs: fused normalization, local reciprocals,
    //    3-buffer ring with one barrier per iteration
    k_out<<<dim3(Dd / 128, Ll / 128, 2 * Bb), 256, SMEM_OUT>>>(
        eatt, rsum, csum, i1h, i2h, out);
}